// round 1
// baseline (speedup 1.0000x reference)
#include <cuda_runtime.h>
#include <cstdint>
#include <cstddef>

#define BM 64
#define BN 64
#define DH 64
#define NTHREADS 128
#define QK_STRIDE 68   // pad 4 floats: 2-way bank conflicts on transpose store, 16B-aligned rows

__device__ __forceinline__ float fast_exp2(float x) {
    float r;
    asm("ex2.approx.ftz.f32 %0, %1;" : "=f"(r) : "f"(x));
    return r;
}

// One CTA: 64 query rows of one (b,h). 128 threads as 8 (ty) x 16 (tx),
// each thread owns an 8-row x 4-col micro-tile of the 64x64 score tile and
// the matching 8x4 micro-tile of the 64x64 output accumulator.
__global__ void __launch_bounds__(NTHREADS, 1) fattn_fwd(
    const float* __restrict__ Q, const float* __restrict__ K,
    const float* __restrict__ V, float* __restrict__ O, int S) {
    extern __shared__ float sm[];
    float* Qs  = sm;                      // Q^T  [DH][QK_STRIDE]  (scaled by 1/8 * log2e)
    float* KPs = sm + DH * QK_STRIDE;     // K^T  [DH][QK_STRIDE]  / P [BM][BN] (aliased)
    float* Vs  = sm + 2 * DH * QK_STRIDE; // V    [BN][DH]

    const int tid = threadIdx.x;
    const int ty  = tid >> 4;   // 0..7  : row group (8 rows each)
    const int tx  = tid & 15;   // 0..15 : col group (4 cols each)
    const int qm  = gridDim.x - 1 - blockIdx.x;  // heavy (late-diagonal) blocks first
    const int bh  = blockIdx.y;

    const float* Qp = Q + ((size_t)bh * S + (size_t)qm * BM) * DH;
    const float* Kp = K + (size_t)bh * S * DH;
    const float* Vp = V + (size_t)bh * S * DH;
    float*       Op = O + ((size_t)bh * S + (size_t)qm * BM) * DH;

    // ref scales q and k each by 1/sqrt(sqrt(D)) -> logits * 1/sqrt(D) = 1/8.
    // Fold 1/8 and log2(e) into Q so softmax runs in exp2 domain.
    const float qscale = 0.125f * 1.4426950408889634f;

    // ---- load Q tile, transposed + scaled ----
#pragma unroll
    for (int it = 0; it < (BM * DH / 4) / NTHREADS; ++it) {
        int i = it * NTHREADS + tid;
        int r = i >> 4, d4 = i & 15;
        float4 v = reinterpret_cast<const float4*>(Qp)[i];
        Qs[(4 * d4 + 0) * QK_STRIDE + r] = v.x * qscale;
        Qs[(4 * d4 + 1) * QK_STRIDE + r] = v.y * qscale;
        Qs[(4 * d4 + 2) * QK_STRIDE + r] = v.z * qscale;
        Qs[(4 * d4 + 3) * QK_STRIDE + r] = v.w * qscale;
    }

    float m_i[8], l_i[8], acc[8][4];
#pragma unroll
    for (int i = 0; i < 8; ++i) {
        m_i[i] = -1e30f;
        l_i[i] = 0.f;
#pragma unroll
        for (int c = 0; c < 4; ++c) acc[i][c] = 0.f;
    }

    const int ntiles = qm + 1;  // causal: kv tiles 0..qm
    for (int t = 0; t < ntiles; ++t) {
        __syncthreads();  // prior PV done reading Ps(=KPs)/Vs before reload

        // ---- load K tile (transposed) and V tile ----
        const float4* K4 = reinterpret_cast<const float4*>(Kp + (size_t)t * BN * DH);
        const float4* V4 = reinterpret_cast<const float4*>(Vp + (size_t)t * BN * DH);
#pragma unroll
        for (int it = 0; it < (BN * DH / 4) / NTHREADS; ++it) {
            int i = it * NTHREADS + tid;
            int r = i >> 4, d4 = i & 15;
            float4 kv = K4[i];
            KPs[(4 * d4 + 0) * QK_STRIDE + r] = kv.x;
            KPs[(4 * d4 + 1) * QK_STRIDE + r] = kv.y;
            KPs[(4 * d4 + 2) * QK_STRIDE + r] = kv.z;
            KPs[(4 * d4 + 3) * QK_STRIDE + r] = kv.w;
            reinterpret_cast<float4*>(Vs)[i] = V4[i];
        }
        __syncthreads();

        // ---- scores: S = (Q*scale) @ K^T, 8x4 micro-tile per thread ----
        float s[8][4];
#pragma unroll
        for (int i = 0; i < 8; ++i)
#pragma unroll
            for (int c = 0; c < 4; ++c) s[i][c] = 0.f;

#pragma unroll 8
        for (int d = 0; d < DH; ++d) {
            float4 qa = *reinterpret_cast<const float4*>(&Qs[d * QK_STRIDE + ty * 8]);
            float4 qb = *reinterpret_cast<const float4*>(&Qs[d * QK_STRIDE + ty * 8 + 4]);
            float4 kk = *reinterpret_cast<const float4*>(&KPs[d * QK_STRIDE + tx * 4]);
            float qv[8] = {qa.x, qa.y, qa.z, qa.w, qb.x, qb.y, qb.z, qb.w};
            float kv[4] = {kk.x, kk.y, kk.z, kk.w};
#pragma unroll
            for (int i = 0; i < 8; ++i)
#pragma unroll
                for (int c = 0; c < 4; ++c) s[i][c] += qv[i] * kv[c];
        }

        // ---- causal mask (diagonal tile only; BM==BN so local compare) ----
        if (t == qm) {
#pragma unroll
            for (int i = 0; i < 8; ++i)
#pragma unroll
                for (int c = 0; c < 4; ++c)
                    if (tx * 4 + c > ty * 8 + i) s[i][c] = -1e30f;
        }

        __syncthreads();  // all threads done reading K^T before P overwrites it

        // ---- online softmax (exp2 domain) + write P ----
#pragma unroll
        for (int i = 0; i < 8; ++i) {
            float rmax = fmaxf(fmaxf(s[i][0], s[i][1]), fmaxf(s[i][2], s[i][3]));
#pragma unroll
            for (int o = 8; o >= 1; o >>= 1)
                rmax = fmaxf(rmax, __shfl_xor_sync(0xffffffffu, rmax, o));
            float mnew  = fmaxf(m_i[i], rmax);
            float alpha = fast_exp2(m_i[i] - mnew);
            float rsum  = 0.f;
#pragma unroll
            for (int c = 0; c < 4; ++c) {
                float p = fast_exp2(s[i][c] - mnew);
                s[i][c] = p;
                rsum += p;
            }
#pragma unroll
            for (int o = 8; o >= 1; o >>= 1)
                rsum += __shfl_xor_sync(0xffffffffu, rsum, o);
            l_i[i] = l_i[i] * alpha + rsum;
            m_i[i] = mnew;
#pragma unroll
            for (int c = 0; c < 4; ++c) acc[i][c] *= alpha;
            *reinterpret_cast<float4*>(&KPs[(ty * 8 + i) * BN + tx * 4]) =
                make_float4(s[i][0], s[i][1], s[i][2], s[i][3]);
        }
        __syncthreads();

        // ---- O += P @ V ----
#pragma unroll 2
        for (int s4 = 0; s4 < BN / 4; ++s4) {
            float vv[4][4];
#pragma unroll
            for (int k = 0; k < 4; ++k) {
                float4 v4 = *reinterpret_cast<const float4*>(&Vs[(4 * s4 + k) * DH + tx * 4]);
                vv[k][0] = v4.x; vv[k][1] = v4.y; vv[k][2] = v4.z; vv[k][3] = v4.w;
            }
#pragma unroll
            for (int i = 0; i < 8; ++i) {
                float4 p4 = *reinterpret_cast<const float4*>(&KPs[(ty * 8 + i) * BN + 4 * s4]);
#pragma unroll
                for (int c = 0; c < 4; ++c) {
                    acc[i][c] += p4.x * vv[0][c];
                    acc[i][c] += p4.y * vv[1][c];
                    acc[i][c] += p4.z * vv[2][c];
                    acc[i][c] += p4.w * vv[3][c];
                }
            }
        }
    }

    // ---- epilogue: O /= l ----
#pragma unroll
    for (int i = 0; i < 8; ++i) {
        float inv = 1.0f / l_i[i];
        float4 o = make_float4(acc[i][0] * inv, acc[i][1] * inv,
                               acc[i][2] * inv, acc[i][3] * inv);
        reinterpret_cast<float4*>(Op + (size_t)(ty * 8 + i) * DH)[tx] = o;
    }
}

extern "C" void kernel_launch(void* const* d_in, const int* in_sizes, int n_in,
                              void* d_out, int out_size) {
    const float* Q = (const float*)d_in[0];
    const float* K = (const float*)d_in[1];
    const float* V = (const float*)d_in[2];
    float* O = (float*)d_out;

    const int B = 4, H = 16, S = 2048;
    const size_t smem = (size_t)(2 * DH * QK_STRIDE + BN * DH) * sizeof(float);  // 51200 B
    cudaFuncSetAttribute(fattn_fwd, cudaFuncAttributeMaxDynamicSharedMemorySize, (int)smem);

    dim3 grid(S / BM, B * H);
    fattn_fwd<<<grid, NTHREADS, smem>>>(Q, K, V, O, S);
}

// round 2
// speedup vs baseline: 2.9260x; 2.9260x over previous
#include <cuda_runtime.h>
#include <cstdint>
#include <cstddef>

#define BM 128          // q rows per CTA
#define BN 64           // kv cols per tile
#define DH 64           // head dim
#define NTHREADS 128    // 4 warps, each owns 32 q-rows x 64 kv-cols
#define LDS_LD 68       // padded row stride (floats): conflict-free frag loads

__device__ __forceinline__ float fast_exp2(float x) {
    float r;
    asm("ex2.approx.ftz.f32 %0, %1;" : "=f"(r) : "f"(x));
    return r;
}

// round-to-nearest tf32 (keeps 10 mantissa bits, low 13 bits zero)
__device__ __forceinline__ float tf32r(float x) {
    uint32_t u;
    asm("cvt.rna.tf32.f32 %0, %1;" : "=r"(u) : "f"(x));
    return __uint_as_float(u);
}

__device__ __forceinline__ void mma_tf32(float c[4], const uint32_t a[4],
                                         uint32_t b0, uint32_t b1) {
    asm volatile(
        "mma.sync.aligned.m16n8k8.row.col.f32.tf32.tf32.f32 "
        "{%0,%1,%2,%3},{%4,%5,%6,%7},{%8,%9},{%0,%1,%2,%3};"
        : "+f"(c[0]), "+f"(c[1]), "+f"(c[2]), "+f"(c[3])
        : "r"(a[0]), "r"(a[1]), "r"(a[2]), "r"(a[3]), "r"(b0), "r"(b1));
}

__global__ void __launch_bounds__(NTHREADS, 2) fattn_tc(
    const float* __restrict__ Q, const float* __restrict__ K,
    const float* __restrict__ V, float* __restrict__ O, int S) {
    extern __shared__ float sm[];
    float* Qs = sm;                          // [BM][LDS_LD] tf32-rounded, scaled
    float* Ks = Qs + BM * LDS_LD;            // [BN][LDS_LD] tf32-rounded
    float* Vs = Ks + BN * LDS_LD;            // [BN][LDS_LD] raw f32 (trunc in mma)
    float* Ps = Vs + BN * LDS_LD;            // [BM][LDS_LD] softmax probs (tf32)

    const int tid  = threadIdx.x;
    const int w    = tid >> 5;
    const int lane = tid & 31;
    const int gid  = lane >> 2;   // 0..7
    const int tig  = lane & 3;    // 0..3
    const int qb   = gridDim.x - 1 - blockIdx.x;   // heavy diagonal blocks first
    const int bh   = blockIdx.y;
    const int rbase = 32 * w;                      // warp's first local q-row

    const float* Qp = Q + ((size_t)bh * S + (size_t)qb * BM) * DH;
    const float* Kp = K + (size_t)bh * S * DH;
    const float* Vp = V + (size_t)bh * S * DH;
    float*       Op = O + ((size_t)bh * S + (size_t)qb * BM) * DH;

    // ref: q*=D^-1/4, k*=D^-1/4 -> logits/8. Fold 1/8*log2(e) into Q (exp2 domain).
    const float qscale = 0.125f * 1.4426950408889634f;

    // ---- load Q tile: scale + tf32-round ----
#pragma unroll
    for (int it = 0; it < (BM * DH / 4) / NTHREADS; ++it) {
        int i = it * NTHREADS + tid;
        int r = i >> 4, c4 = i & 15;
        float4 v = reinterpret_cast<const float4*>(Qp)[i];
        float4 o;
        o.x = tf32r(v.x * qscale); o.y = tf32r(v.y * qscale);
        o.z = tf32r(v.z * qscale); o.w = tf32r(v.w * qscale);
        *reinterpret_cast<float4*>(&Qs[r * LDS_LD + 4 * c4]) = o;
    }

    // per-thread state: 4 rows (j): mtile=j>>1 at rbase+16*(j>>1), half=j&1 (+8)
    float m_i[4], l_i[4];       // l_i holds THIS thread's partial row sum
    float oc[2][8][4];          // [mtile][ntile(D)][creg] output accum
#pragma unroll
    for (int j = 0; j < 4; ++j) { m_i[j] = -1e30f; l_i[j] = 0.f; }
#pragma unroll
    for (int m = 0; m < 2; ++m)
#pragma unroll
        for (int n = 0; n < 8; ++n)
#pragma unroll
            for (int c = 0; c < 4; ++c) oc[m][n][c] = 0.f;

    const int row_g0 = qb * BM;       // global row of local row 0
    const int ntiles = 2 * qb + 2;    // causal coverage of 128 rows by 64-col tiles
    const int tmask  = 2 * qb;        // tiles >= this need the causal mask

    for (int t = 0; t < ntiles; ++t) {
        __syncthreads();   // previous tile's QK (Ks) and PV (Vs) reads complete

        // ---- load K (tf32-rounded) and V tiles ----
        const float4* K4 = reinterpret_cast<const float4*>(Kp + (size_t)t * BN * DH);
        const float4* V4 = reinterpret_cast<const float4*>(Vp + (size_t)t * BN * DH);
#pragma unroll
        for (int it = 0; it < (BN * DH / 4) / NTHREADS; ++it) {
            int i = it * NTHREADS + tid;
            int r = i >> 4, c4 = i & 15;
            float4 kv = K4[i];
            float4 ko;
            ko.x = tf32r(kv.x); ko.y = tf32r(kv.y);
            ko.z = tf32r(kv.z); ko.w = tf32r(kv.w);
            *reinterpret_cast<float4*>(&Ks[r * LDS_LD + 4 * c4]) = ko;
            *reinterpret_cast<float4*>(&Vs[r * LDS_LD + 4 * c4]) = V4[i];
        }
        __syncthreads();

        // ---- S = Q @ K^T via m16n8k8 tf32 ----
        float sc[2][8][4];
#pragma unroll
        for (int m = 0; m < 2; ++m)
#pragma unroll
            for (int n = 0; n < 8; ++n)
#pragma unroll
                for (int c = 0; c < 4; ++c) sc[m][n][c] = 0.f;

#pragma unroll
        for (int k8 = 0; k8 < 8; ++k8) {
            const int kc = 8 * k8;
            uint32_t a[2][4];
#pragma unroll
            for (int m = 0; m < 2; ++m) {
                const int r0 = rbase + 16 * m + gid;
                a[m][0] = __float_as_uint(Qs[r0 * LDS_LD + kc + tig]);
                a[m][1] = __float_as_uint(Qs[(r0 + 8) * LDS_LD + kc + tig]);
                a[m][2] = __float_as_uint(Qs[r0 * LDS_LD + kc + tig + 4]);
                a[m][3] = __float_as_uint(Qs[(r0 + 8) * LDS_LD + kc + tig + 4]);
            }
#pragma unroll
            for (int n = 0; n < 8; ++n) {
                uint32_t b0 = __float_as_uint(Ks[(8 * n + gid) * LDS_LD + kc + tig]);
                uint32_t b1 = __float_as_uint(Ks[(8 * n + gid) * LDS_LD + kc + tig + 4]);
                mma_tf32(sc[0][n], a[0], b0, b1);
                mma_tf32(sc[1][n], a[1], b0, b1);
            }
        }

        // ---- online softmax (exp2 domain), P -> smem ----
        const bool do_mask = (t >= tmask);
#pragma unroll
        for (int j = 0; j < 4; ++j) {
            const int mt = j >> 1, hi = j & 1, i0 = 2 * hi;
            const int rloc = rbase + 16 * mt + 8 * hi + gid;
            const int rglb = row_g0 + rloc;

            if (do_mask) {
#pragma unroll
                for (int n = 0; n < 8; ++n) {
                    int col = t * BN + 8 * n + 2 * tig;
                    if (col > rglb)     sc[mt][n][i0]     = -1e30f;
                    if (col + 1 > rglb) sc[mt][n][i0 + 1] = -1e30f;
                }
            }
            float mx = m_i[j];
#pragma unroll
            for (int n = 0; n < 8; ++n)
                mx = fmaxf(mx, fmaxf(sc[mt][n][i0], sc[mt][n][i0 + 1]));
            mx = fmaxf(mx, __shfl_xor_sync(0xffffffffu, mx, 1));
            mx = fmaxf(mx, __shfl_xor_sync(0xffffffffu, mx, 2));

            const float alpha = fast_exp2(m_i[j] - mx);
            m_i[j] = mx;
            float psum = 0.f;
#pragma unroll
            for (int n = 0; n < 8; ++n) {
                float p0 = fast_exp2(sc[mt][n][i0] - mx);
                float p1 = fast_exp2(sc[mt][n][i0 + 1] - mx);
                psum += p0 + p1;
                float2 pw = make_float2(tf32r(p0), tf32r(p1));
                *reinterpret_cast<float2*>(&Ps[rloc * LDS_LD + 8 * n + 2 * tig]) = pw;
                oc[mt][n == 0 ? 0 : n][0] = oc[mt][n][0];  // no-op; keep structure
            }
            l_i[j] = l_i[j] * alpha + psum;
#pragma unroll
            for (int n = 0; n < 8; ++n) {
                oc[mt][n][i0]     *= alpha;
                oc[mt][n][i0 + 1] *= alpha;
            }
        }
        __syncwarp();   // P rows are warp-private: warp-level visibility suffices

        // ---- O += P @ V via m16n8k8 tf32 ----
#pragma unroll
        for (int k8 = 0; k8 < 8; ++k8) {
            const int kc = 8 * k8;   // kv index within tile
            uint32_t a[2][4];
#pragma unroll
            for (int m = 0; m < 2; ++m) {
                const int r0 = rbase + 16 * m + gid;
                a[m][0] = __float_as_uint(Ps[r0 * LDS_LD + kc + tig]);
                a[m][1] = __float_as_uint(Ps[(r0 + 8) * LDS_LD + kc + tig]);
                a[m][2] = __float_as_uint(Ps[r0 * LDS_LD + kc + tig + 4]);
                a[m][3] = __float_as_uint(Ps[(r0 + 8) * LDS_LD + kc + tig + 4]);
            }
#pragma unroll
            for (int n = 0; n < 8; ++n) {
                uint32_t b0 = __float_as_uint(Vs[(kc + tig) * LDS_LD + 8 * n + gid]);
                uint32_t b1 = __float_as_uint(Vs[(kc + tig + 4) * LDS_LD + 8 * n + gid]);
                mma_tf32(oc[0][n], a[0], b0, b1);
                mma_tf32(oc[1][n], a[1], b0, b1);
            }
        }
    }

    // ---- epilogue: finish l reduction across quad, divide, store ----
#pragma unroll
    for (int j = 0; j < 4; ++j) {
        const int mt = j >> 1, hi = j & 1, i0 = 2 * hi;
        const int rloc = rbase + 16 * mt + 8 * hi + gid;
        float l = l_i[j];
        l += __shfl_xor_sync(0xffffffffu, l, 1);
        l += __shfl_xor_sync(0xffffffffu, l, 2);
        const float inv = 1.0f / l;
#pragma unroll
        for (int n = 0; n < 8; ++n) {
            float2 o = make_float2(oc[mt][n][i0] * inv, oc[mt][n][i0 + 1] * inv);
            *reinterpret_cast<float2*>(&Op[(size_t)rloc * DH + 8 * n + 2 * tig]) = o;
        }
    }
}

extern "C" void kernel_launch(void* const* d_in, const int* in_sizes, int n_in,
                              void* d_out, int out_size) {
    const float* Q = (const float*)d_in[0];
    const float* K = (const float*)d_in[1];
    const float* V = (const float*)d_in[2];
    float* O = (float*)d_out;

    const int B = 4, H = 16, S = 2048;
    const size_t smem = (size_t)(2 * BM * LDS_LD + 2 * BN * LDS_LD) * sizeof(float); // 104448
    cudaFuncSetAttribute(fattn_tc, cudaFuncAttributeMaxDynamicSharedMemorySize, (int)smem);

    dim3 grid(S / BM, B * H);
    fattn_tc<<<grid, NTHREADS, smem>>>(Q, K, V, O, S);
}

// round 3
// speedup vs baseline: 6.4350x; 2.1992x over previous
#include <cuda_runtime.h>
#include <cuda_fp16.h>
#include <cstdint>
#include <cstddef>

#define BM 128          // q rows per CTA
#define BN 64           // kv cols per tile
#define DH 64           // head dim
#define NTHREADS 128    // 4 warps, each 32 q-rows x 64 kv-cols
#define LDQ 72          // half-element stride (144B rows): conflict-free frags
#define LDK 72
#define LDV 72

__device__ __forceinline__ float fast_exp2(float x) {
    float r;
    asm("ex2.approx.ftz.f32 %0, %1;" : "=f"(r) : "f"(x));
    return r;
}

__device__ __forceinline__ uint32_t packh2(float lo, float hi) {
    __half2 h = __floats2half2_rn(lo, hi);
    return *reinterpret_cast<uint32_t*>(&h);
}

__device__ __forceinline__ void mma_f16(float c[4], uint32_t a0, uint32_t a1,
                                        uint32_t a2, uint32_t a3,
                                        uint32_t b0, uint32_t b1) {
    asm volatile(
        "mma.sync.aligned.m16n8k16.row.col.f32.f16.f16.f32 "
        "{%0,%1,%2,%3},{%4,%5,%6,%7},{%8,%9},{%0,%1,%2,%3};"
        : "+f"(c[0]), "+f"(c[1]), "+f"(c[2]), "+f"(c[3])
        : "r"(a0), "r"(a1), "r"(a2), "r"(a3), "r"(b0), "r"(b1));
}

__device__ __forceinline__ void ldsm_x4_t(uint32_t& d0, uint32_t& d1,
                                          uint32_t& d2, uint32_t& d3, uint32_t addr) {
    asm volatile(
        "ldmatrix.sync.aligned.m8n8.x4.trans.shared.b16 {%0,%1,%2,%3}, [%4];"
        : "=r"(d0), "=r"(d1), "=r"(d2), "=r"(d3) : "r"(addr));
}

__global__ void __launch_bounds__(NTHREADS, 2) fattn_h16(
    const float* __restrict__ Q, const float* __restrict__ K,
    const float* __restrict__ V, float* __restrict__ O, int S) {
    extern __shared__ __half sm[];
    __half* Qs = sm;                 // [BM][LDQ] fp16, scaled
    __half* Ks = Qs + BM * LDQ;      // [BN][LDK] fp16
    __half* Vs = Ks + BN * LDK;      // [BN][LDV] fp16 (row-major; ldmatrix.trans)

    const int tid  = threadIdx.x;
    const int w    = tid >> 5;
    const int lane = tid & 31;
    const int gid  = lane >> 2;     // 0..7
    const int tig  = lane & 3;      // 0..3
    const int qb   = gridDim.x - 1 - blockIdx.x;  // heavy diagonal blocks first
    const int bh   = blockIdx.y;
    const int rbase = 32 * w;

    const float* Qp = Q + ((size_t)bh * S + (size_t)qb * BM) * DH;
    const float* Kp = K + (size_t)bh * S * DH;
    const float* Vp = V + (size_t)bh * S * DH;
    float*       Op = O + ((size_t)bh * S + (size_t)qb * BM) * DH;

    // smem base (u32) for ldmatrix addressing
    uint32_t vbase;
    {
        uint32_t b;
        asm("{ .reg .u64 t; cvta.to.shared.u64 t, %1; cvt.u32.u64 %0, t; }"
            : "=r"(b) : "l"(Vs));
        vbase = b;
    }

    // ref: q*=D^-1/4, k*=D^-1/4 -> logits/8. Fold 1/8*log2(e) into Q (exp2 domain).
    const float qscale = 0.125f * 1.4426950408889634f;

    // ---- Q tile: gmem f32 -> fp16 smem (scaled) ----
#pragma unroll
    for (int it = 0; it < (BM * DH / 4) / NTHREADS; ++it) {
        int i = it * NTHREADS + tid;
        int r = i >> 4, c4 = i & 15;
        float4 v = reinterpret_cast<const float4*>(Qp)[i];
        uint2 p;
        p.x = packh2(v.x * qscale, v.y * qscale);
        p.y = packh2(v.z * qscale, v.w * qscale);
        *reinterpret_cast<uint2*>(&Qs[r * LDQ + 4 * c4]) = p;
    }

    float m_i[4], l_i[4];
    float oc[2][8][4];
#pragma unroll
    for (int j = 0; j < 4; ++j) { m_i[j] = -1e30f; l_i[j] = 0.f; }
#pragma unroll
    for (int m = 0; m < 2; ++m)
#pragma unroll
        for (int n = 0; n < 8; ++n)
#pragma unroll
            for (int c = 0; c < 4; ++c) oc[m][n][c] = 0.f;

    const int row_g0 = qb * BM;
    const int ntiles = 2 * qb + 2;
    const int tmask  = 2 * qb;

    // ---- prefetch tile 0 into registers ----
    float4 kreg[8], vreg[8];
    {
        const float4* K4 = reinterpret_cast<const float4*>(Kp);
        const float4* V4 = reinterpret_cast<const float4*>(Vp);
#pragma unroll
        for (int it = 0; it < 8; ++it) {
            int i = it * NTHREADS + tid;
            kreg[it] = K4[i];
            vreg[it] = V4[i];
        }
    }

    for (int t = 0; t < ntiles; ++t) {
        __syncthreads();   // prior tile's Ks/Vs reads complete

        // ---- STS current tile (f32 regs -> fp16 smem) ----
#pragma unroll
        for (int it = 0; it < 8; ++it) {
            int i = it * NTHREADS + tid;
            int r = i >> 4, c4 = i & 15;
            uint2 pk, pv;
            pk.x = packh2(kreg[it].x, kreg[it].y);
            pk.y = packh2(kreg[it].z, kreg[it].w);
            pv.x = packh2(vreg[it].x, vreg[it].y);
            pv.y = packh2(vreg[it].z, vreg[it].w);
            *reinterpret_cast<uint2*>(&Ks[r * LDK + 4 * c4]) = pk;
            *reinterpret_cast<uint2*>(&Vs[r * LDV + 4 * c4]) = pv;
        }
        __syncthreads();

        // ---- issue LDG for tile t+1 (hidden behind compute below) ----
        if (t + 1 < ntiles) {
            const float4* K4 = reinterpret_cast<const float4*>(Kp + (size_t)(t + 1) * BN * DH);
            const float4* V4 = reinterpret_cast<const float4*>(Vp + (size_t)(t + 1) * BN * DH);
#pragma unroll
            for (int it = 0; it < 8; ++it) {
                int i = it * NTHREADS + tid;
                kreg[it] = K4[i];
                vreg[it] = V4[i];
            }
        }

        // ---- S = Q @ K^T (fp16 m16n8k16) ----
        float sc[2][8][4];
#pragma unroll
        for (int m = 0; m < 2; ++m)
#pragma unroll
            for (int n = 0; n < 8; ++n)
#pragma unroll
                for (int c = 0; c < 4; ++c) sc[m][n][c] = 0.f;

#pragma unroll
        for (int k16 = 0; k16 < 4; ++k16) {
            const int kc = 16 * k16;
            uint32_t a[2][4];
#pragma unroll
            for (int m = 0; m < 2; ++m) {
                const int r0 = rbase + 16 * m + gid;
                a[m][0] = *reinterpret_cast<const uint32_t*>(&Qs[r0 * LDQ + kc + 2 * tig]);
                a[m][1] = *reinterpret_cast<const uint32_t*>(&Qs[(r0 + 8) * LDQ + kc + 2 * tig]);
                a[m][2] = *reinterpret_cast<const uint32_t*>(&Qs[r0 * LDQ + kc + 2 * tig + 8]);
                a[m][3] = *reinterpret_cast<const uint32_t*>(&Qs[(r0 + 8) * LDQ + kc + 2 * tig + 8]);
            }
#pragma unroll
            for (int n = 0; n < 8; ++n) {
                uint32_t b0 = *reinterpret_cast<const uint32_t*>(&Ks[(8 * n + gid) * LDK + kc + 2 * tig]);
                uint32_t b1 = *reinterpret_cast<const uint32_t*>(&Ks[(8 * n + gid) * LDK + kc + 2 * tig + 8]);
                mma_f16(sc[0][n], a[0][0], a[0][1], a[0][2], a[0][3], b0, b1);
                mma_f16(sc[1][n], a[1][0], a[1][1], a[1][2], a[1][3], b0, b1);
            }
        }

        // ---- online softmax (exp2 domain); p stays in sc regs ----
        const bool do_mask = (t >= tmask);
#pragma unroll
        for (int j = 0; j < 4; ++j) {
            const int mt = j >> 1, hi = j & 1, i0 = 2 * hi;
            const int rglb = row_g0 + rbase + 16 * mt + 8 * hi + gid;

            if (do_mask) {
#pragma unroll
                for (int n = 0; n < 8; ++n) {
                    int col = t * BN + 8 * n + 2 * tig;
                    if (col > rglb)     sc[mt][n][i0]     = -1e30f;
                    if (col + 1 > rglb) sc[mt][n][i0 + 1] = -1e30f;
                }
            }
            float mx = m_i[j];
#pragma unroll
            for (int n = 0; n < 8; ++n)
                mx = fmaxf(mx, fmaxf(sc[mt][n][i0], sc[mt][n][i0 + 1]));
            mx = fmaxf(mx, __shfl_xor_sync(0xffffffffu, mx, 1));
            mx = fmaxf(mx, __shfl_xor_sync(0xffffffffu, mx, 2));

            const float alpha = fast_exp2(m_i[j] - mx);
            m_i[j] = mx;
            float psum = 0.f;
#pragma unroll
            for (int n = 0; n < 8; ++n) {
                float p0 = fast_exp2(sc[mt][n][i0] - mx);
                float p1 = fast_exp2(sc[mt][n][i0 + 1] - mx);
                sc[mt][n][i0] = p0;
                sc[mt][n][i0 + 1] = p1;
                psum += p0 + p1;
            }
            l_i[j] = l_i[j] * alpha + psum;
#pragma unroll
            for (int n = 0; n < 8; ++n) {
                oc[mt][n][i0]     *= alpha;
                oc[mt][n][i0 + 1] *= alpha;
            }
        }

        // ---- O += P @ V : A-frag packed from sc regs, B via ldmatrix.trans ----
#pragma unroll
        for (int k16 = 0; k16 < 4; ++k16) {
            const int kc = 16 * k16;
            uint32_t a[2][4];
#pragma unroll
            for (int m = 0; m < 2; ++m) {
                a[m][0] = packh2(sc[m][2 * k16][0],     sc[m][2 * k16][1]);
                a[m][1] = packh2(sc[m][2 * k16][2],     sc[m][2 * k16][3]);
                a[m][2] = packh2(sc[m][2 * k16 + 1][0], sc[m][2 * k16 + 1][1]);
                a[m][3] = packh2(sc[m][2 * k16 + 1][2], sc[m][2 * k16 + 1][3]);
            }
#pragma unroll
            for (int np = 0; np < 4; ++np) {
                // lanes 0-15: rows kc+(lane&15), col 16*np ; lanes 16-31: col 16*np+8
                uint32_t addr = vbase +
                    2u * ((uint32_t)(kc + (lane & 15)) * LDV + 16u * np + 8u * (lane >> 4));
                uint32_t b0, b1, b2, b3;
                ldsm_x4_t(b0, b1, b2, b3, addr);
                mma_f16(oc[0][2 * np],     a[0][0], a[0][1], a[0][2], a[0][3], b0, b1);
                mma_f16(oc[1][2 * np],     a[1][0], a[1][1], a[1][2], a[1][3], b0, b1);
                mma_f16(oc[0][2 * np + 1], a[0][0], a[0][1], a[0][2], a[0][3], b2, b3);
                mma_f16(oc[1][2 * np + 1], a[1][0], a[1][1], a[1][2], a[1][3], b2, b3);
            }
        }
    }

    // ---- epilogue: finish l across quad, normalize, store ----
#pragma unroll
    for (int j = 0; j < 4; ++j) {
        const int mt = j >> 1, hi = j & 1, i0 = 2 * hi;
        const int rloc = rbase + 16 * mt + 8 * hi + gid;
        float l = l_i[j];
        l += __shfl_xor_sync(0xffffffffu, l, 1);
        l += __shfl_xor_sync(0xffffffffu, l, 2);
        const float inv = 1.0f / l;
#pragma unroll
        for (int n = 0; n < 8; ++n) {
            float2 o = make_float2(oc[mt][n][i0] * inv, oc[mt][n][i0 + 1] * inv);
            *reinterpret_cast<float2*>(&Op[(size_t)rloc * DH + 8 * n + 2 * tig]) = o;
        }
    }
}

extern "C" void kernel_launch(void* const* d_in, const int* in_sizes, int n_in,
                              void* d_out, int out_size) {
    const float* Q = (const float*)d_in[0];
    const float* K = (const float*)d_in[1];
    const float* V = (const float*)d_in[2];
    float* O = (float*)d_out;

    const int B = 4, H = 16, S = 2048;
    const size_t smem = (size_t)(BM * LDQ + BN * LDK + BN * LDV) * sizeof(__half); // 36864 B
    cudaFuncSetAttribute(fattn_h16, cudaFuncAttributeMaxDynamicSharedMemorySize, (int)smem);

    dim3 grid(S / BM, B * H);
    fattn_h16<<<grid, NTHREADS, smem>>>(Q, K, V, O, S);
}